// round 7
// baseline (speedup 1.0000x reference)
#include <cuda_runtime.h>

// Problem constants
#define NB 16
#define NT 256
#define NK 128
#define ND 256   // D_E == D_K == 256
#define NU 128

// Scratch (allocation-free rule: __device__ globals)
__device__ float g_e[NB * NT * NU];     // [b*NT + t][u]   (e-proj + b1)
__device__ float g_kpT[NB * NU * NK];   // [b][u][k]       (k-proj + b2, transposed)

__device__ __forceinline__ float tanh_fast(float x) {
    float y;
    asm("tanh.approx.f32 %0, %1;" : "=f"(y) : "f"(x));
    return y;
}
// Packed f32x2 ops (sm_100+): one FFMA2 = 2 fp32 FMAs on the fma pipe.
__device__ __forceinline__ unsigned long long fma2(unsigned long long a,
                                                   unsigned long long b,
                                                   unsigned long long c) {
    unsigned long long d;
    asm("fma.rn.f32x2 %0, %1, %2, %3;" : "=l"(d) : "l"(a), "l"(b), "l"(c));
    return d;
}
__device__ __forceinline__ unsigned long long add2(unsigned long long a,
                                                   unsigned long long b) {
    unsigned long long d;
    asm("add.rn.f32x2 %0, %1, %2;" : "=l"(d) : "l"(a), "l"(b));
    return d;
}
__device__ __forceinline__ float2 u2f(unsigned long long v) {
    float2 r;
    asm("mov.b64 {%0, %1}, %2;" : "=f"(r.x), "=f"(r.y) : "l"(v));
    return r;
}

// ---------------------------------------------------------------------------
// Projection kernel: blocks [0,256) do e = enc @ W1 + b1  (4096 rows)
//                    blocks [256,384) do kp = knw @ W2 + b2 (2048 rows, transposed store)
// 16 rows x 128 cols per block. A tile stored DUPLICATED (a,a) so the inner
// loop is pure LDS.64/LDS.128 + FFMA2 with zero packing movs.
// ---------------------------------------------------------------------------
__global__ __launch_bounds__(256) void proj_kernel(
    const float* __restrict__ enc, const float* __restrict__ knw,
    const float* __restrict__ W1, const float* __restrict__ b1,
    const float* __restrict__ W2, const float* __restrict__ b2)
{
    const int blk = blockIdx.x;
    const bool isE = (blk < 256);
    const float* __restrict__ A    = isE ? enc : knw;
    const float* __restrict__ W    = isE ? W1  : W2;
    const float* __restrict__ bias = isE ? b1  : b2;
    const int row0 = (isE ? blk : (blk - 256)) * 16;

    __shared__ float2 As2[16][32];    // duplicated (a,a)
    __shared__ float  Bs[32][128];

    const int tid = threadIdx.x;
    const int tx  = tid & 31;   // lane -> 4 output cols
    const int ty  = tid >> 5;   // warp -> 2 output rows

    unsigned long long a00 = 0ull, a01 = 0ull;   // row0: cols (0,1) and (2,3)
    unsigned long long a10 = 0ull, a11 = 0ull;   // row1

    for (int kc = 0; kc < ND; kc += 32) {
        if (tid < 128) {
            int r  = tid >> 3;   // 0..15
            int c4 = tid & 7;    // 0..7
            float4 a = *(const float4*)&A[(row0 + r) * ND + kc + c4 * 4];
            As2[r][c4 * 4 + 0] = make_float2(a.x, a.x);
            As2[r][c4 * 4 + 1] = make_float2(a.y, a.y);
            As2[r][c4 * 4 + 2] = make_float2(a.z, a.z);
            As2[r][c4 * 4 + 3] = make_float2(a.w, a.w);
        }
        #pragma unroll
        for (int i = 0; i < 4; i++) {
            int lin = tid + i * 256;
            int r   = lin >> 5;
            int c4  = lin & 31;
            *(float4*)&Bs[r][c4 * 4] = *(const float4*)&W[(kc + r) * NU + c4 * 4];
        }
        __syncthreads();

        #pragma unroll
        for (int kk = 0; kk < 32; kk++) {
            ulonglong2 bv = *(const ulonglong2*)&Bs[kk][tx * 4];
            unsigned long long av0 = *(const unsigned long long*)&As2[ty * 2 + 0][kk];
            unsigned long long av1 = *(const unsigned long long*)&As2[ty * 2 + 1][kk];
            a00 = fma2(av0, bv.x, a00);
            a01 = fma2(av0, bv.y, a01);
            a10 = fma2(av1, bv.x, a10);
            a11 = fma2(av1, bv.y, a11);
        }
        __syncthreads();
    }

    float2 r00 = u2f(a00), r01 = u2f(a01), r10 = u2f(a10), r11 = u2f(a11);
    float4 bb = *(const float4*)&bias[tx * 4];
    float4 acc0 = make_float4(r00.x + bb.x, r00.y + bb.y, r01.x + bb.z, r01.y + bb.w);
    float4 acc1 = make_float4(r10.x + bb.x, r10.y + bb.y, r11.x + bb.z, r11.y + bb.w);

    const int r0 = row0 + ty * 2;
    if (isE) {
        *(float4*)&g_e[(r0 + 0) * NU + tx * 4] = acc0;
        *(float4*)&g_e[(r0 + 1) * NU + tx * 4] = acc1;
    } else {
        int b0 = r0 >> 7;
        int k0 = r0 & 127;
        float* dst = &g_kpT[b0 * NU * NK];
        dst[(4 * tx + 0) * NK + k0] = acc0.x;
        dst[(4 * tx + 1) * NK + k0] = acc0.y;
        dst[(4 * tx + 2) * NK + k0] = acc0.z;
        dst[(4 * tx + 3) * NK + k0] = acc0.w;
        dst[(4 * tx + 0) * NK + k0 + 1] = acc1.x;
        dst[(4 * tx + 1) * NK + k0 + 1] = acc1.y;
        dst[(4 * tx + 2) * NK + k0 + 1] = acc1.z;
        dst[(4 * tx + 3) * NK + k0 + 1] = acc1.w;
    }
}

// ---------------------------------------------------------------------------
// Fused score + softmax + context.
// Grid (NT/32, NB), 512 threads (16 warps).
//  score:   warp w owns t = {2w, 2w+1}, lane owns k = 4*lane..+3  (MUFU-bound)
//  context: warp w owns t-quad (w&7), k-half (w>>3): halves smem traffic,
//           partials reduced through smem.
// smem regions time-multiplexed:
//   [0,128K)      know_s [k][d]
//   [128K,192K)   kpT_s [u][k]  ->  attn2 (float2 dup, 32K)  ->  red (64K)
//   [192K,208K)   e_s [lt][u]
//   [208K,+512)   v_s
// ---------------------------------------------------------------------------
__global__ __launch_bounds__(512) void fused_kernel(
    const float* __restrict__ knw, const float* __restrict__ V,
    float* __restrict__ out)
{
    extern __shared__ float smem[];
    float*  know_s = smem;                      // 32768 floats
    float*  kpT_s  = smem + NK * ND;            // 16384 floats (multiplexed)
    float*  e_s    = kpT_s + NU * NK;           // 4096 floats
    float*  v_s    = e_s + 32 * NU;             // 128 floats
    float2* attn2  = (float2*)kpT_s;            // [32][128] duplicated (p,p)
    float*  red    = kpT_s;                     // [2][32][256] partial contexts

    const int b    = blockIdx.y;
    const int t0   = blockIdx.x * 32;
    const int tid  = threadIdx.x;
    const int lane = tid & 31;
    const int w    = tid >> 5;

    // ---- stage (float4, coalesced) ----
    {
        const float4* s = (const float4*)(knw + b * NK * ND);
        float4* d = (float4*)know_s;
        #pragma unroll
        for (int i = 0; i < 16; i++) d[tid + i * 512] = s[tid + i * 512];
    }
    {
        const float4* s = (const float4*)(g_kpT + b * NU * NK);
        float4* d = (float4*)kpT_s;
        #pragma unroll
        for (int i = 0; i < 8; i++) d[tid + i * 512] = s[tid + i * 512];
    }
    {
        const float4* s = (const float4*)(g_e + (b * NT + t0) * NU);
        float4* d = (float4*)e_s;
        #pragma unroll
        for (int i = 0; i < 2; i++) d[tid + i * 512] = s[tid + i * 512];
    }
    if (tid < NU) v_s[tid] = V[tid];
    __syncthreads();

    // ---- score ----
    const int lt0 = 2 * w;
    float4 s0 = make_float4(0.f, 0.f, 0.f, 0.f);
    float4 s1 = make_float4(0.f, 0.f, 0.f, 0.f);
    const float* e0 = &e_s[(lt0 + 0) * NU];
    const float* e1 = &e_s[(lt0 + 1) * NU];

    #pragma unroll 4
    for (int u = 0; u < NU; u++) {
        float4 kp = ((const float4*)&kpT_s[u * NK])[lane];
        float vu  = v_s[u];
        float ev0 = e0[u];
        float ev1 = e1[u];
        s0.x += vu * tanh_fast(ev0 + kp.x);
        s0.y += vu * tanh_fast(ev0 + kp.y);
        s0.z += vu * tanh_fast(ev0 + kp.z);
        s0.w += vu * tanh_fast(ev0 + kp.w);
        s1.x += vu * tanh_fast(ev1 + kp.x);
        s1.y += vu * tanh_fast(ev1 + kp.y);
        s1.z += vu * tanh_fast(ev1 + kp.z);
        s1.w += vu * tanh_fast(ev1 + kp.w);
    }
    __syncthreads();   // kpT_s region retires; becomes attn2

    // ---- softmax (per t within warp); bV cancels ----
    #pragma unroll
    for (int tt = 0; tt < 2; tt++) {
        float4 sv = tt ? s1 : s0;
        float m = fmaxf(fmaxf(sv.x, sv.y), fmaxf(sv.z, sv.w));
        #pragma unroll
        for (int o = 16; o > 0; o >>= 1)
            m = fmaxf(m, __shfl_xor_sync(0xffffffffu, m, o));
        float4 p;
        p.x = __expf(sv.x - m);
        p.y = __expf(sv.y - m);
        p.z = __expf(sv.z - m);
        p.w = __expf(sv.w - m);
        float sum = (p.x + p.y) + (p.z + p.w);
        #pragma unroll
        for (int o = 16; o > 0; o >>= 1)
            sum += __shfl_xor_sync(0xffffffffu, sum, o);
        float inv = __fdividef(1.0f, sum);
        p.x *= inv; p.y *= inv; p.z *= inv; p.w *= inv;
        float2* a = &attn2[(lt0 + tt) * NK + 4 * lane];
        a[0] = make_float2(p.x, p.x);
        a[1] = make_float2(p.y, p.y);
        a[2] = make_float2(p.z, p.z);
        a[3] = make_float2(p.w, p.w);
    }
    __syncthreads();

    // ---- context: warp w -> t quad (w&7), k half (w>>3) ----
    const int tq = w & 7;
    const int kh = (w >> 3) * 64;
    unsigned long long c[4][4];
    #pragma unroll
    for (int i = 0; i < 4; i++)
        #pragma unroll
        for (int j = 0; j < 4; j++) c[i][j] = 0ull;

    #pragma unroll 2
    for (int kk = 0; kk < 64; kk++) {
        const int k = kh + kk;
        const float* row = &know_s[k * ND];
        ulonglong2 lo = ((const ulonglong2*)row)[lane];        // d = 4*lane..+3
        ulonglong2 hi = ((const ulonglong2*)row)[lane + 32];   // d = 128+4*lane..+3
        #pragma unroll
        for (int tt = 0; tt < 4; tt++) {
            unsigned long long a =
                *(const unsigned long long*)&attn2[(4 * tq + tt) * NK + k];
            c[tt][0] = fma2(a, lo.x, c[tt][0]);
            c[tt][1] = fma2(a, lo.y, c[tt][1]);
            c[tt][2] = fma2(a, hi.x, c[tt][2]);
            c[tt][3] = fma2(a, hi.y, c[tt][3]);
        }
    }
    __syncthreads();   // attn2 reads done; region becomes red

    // ---- store partials: red[h][lt][d] ----
    {
        const int base = (w >> 3) * 32 * ND;   // h * 8192 floats
        #pragma unroll
        for (int tt = 0; tt < 4; tt++) {
            float* r = &red[base + (4 * tq + tt) * ND];
            ((ulonglong2*)r)[lane]         = make_ulonglong2(c[tt][0], c[tt][1]);
            ((ulonglong2*)(r + 128))[lane] = make_ulonglong2(c[tt][2], c[tt][3]);
        }
    }
    __syncthreads();

    // ---- reduce halves + write out: warp w handles t = {2w, 2w+1} ----
    #pragma unroll
    for (int tt = 0; tt < 2; tt++) {
        const int lt = 2 * w + tt;
        const ulonglong2* p0 = (const ulonglong2*)&red[lt * ND];
        const ulonglong2* p1 = (const ulonglong2*)&red[32 * ND + lt * ND];
        float* o = out + (size_t)(b * NT + t0 + lt) * ND;
        #pragma unroll
        for (int half = 0; half < 2; half++) {
            ulonglong2 x = p0[lane + half * 32];
            ulonglong2 y = p1[lane + half * 32];
            ulonglong2 z = make_ulonglong2(add2(x.x, y.x), add2(x.y, y.y));
            ((ulonglong2*)o)[lane + half * 32] = z;
        }
    }
}

// ---------------------------------------------------------------------------
// Launch
// ---------------------------------------------------------------------------
extern "C" void kernel_launch(void* const* d_in, const int* in_sizes, int n_in,
                              void* d_out, int out_size)
{
    const float* knw = (const float*)d_in[0];   // knowledge_onehot [16,128,256]
    const float* enc = (const float*)d_in[1];   // encoder_outputs  [16,256,256]
    const float* W1  = (const float*)d_in[2];
    const float* b1  = (const float*)d_in[3];
    const float* W2  = (const float*)d_in[4];
    const float* b2  = (const float*)d_in[5];
    const float* V   = (const float*)d_in[6];
    // d_in[7] = bV: cancels in softmax. Unused.

    if (n_in >= 2 && in_sizes[0] == NB * NT * ND && in_sizes[1] == NB * NK * ND) {
        const float* tmp = knw; knw = enc; enc = tmp;
    }

    const int smem_bytes = (NK * ND + NU * NK + 32 * NU + NU) * (int)sizeof(float); // 213504
    cudaFuncSetAttribute(fused_kernel, cudaFuncAttributeMaxDynamicSharedMemorySize,
                         smem_bytes);

    proj_kernel<<<384, 256>>>(enc, knw, W1, b1, W2, b2);

    dim3 grid(NT / 32, NB);
    fused_kernel<<<grid, 512, smem_bytes>>>(knw, V, (float*)d_out);

    (void)n_in; (void)out_size;
}